// round 11
// baseline (speedup 1.0000x reference)
#include <cuda_runtime.h>
#include <cuda_bf16.h>
#include <cstdint>

// ---------------------------------------------------------------------------
// Problem constants
// ---------------------------------------------------------------------------
#define BATCH   2
#define VVOX    100000
#define MROWS   (BATCH * VVOX)     // 200000 voxel rows
#define GX      128
#define GY      128
#define GZ      16
#define CDIM    64
#define NQ      8192
#define KP      8
#define GRIDCELLS (BATCH * GX * GY * GZ)   // 524288
#define RBLOCKS 256

// conv tiling
#define MTILE   256                 // voxel rows per CTA
#define ASTR    68                  // padded smem row stride (floats)
#define BPAD    (64 * ASTR)         // 4352 floats per W_k (padded layout)

// ---------------------------------------------------------------------------
// Device scratch (static allocation only)
// ---------------------------------------------------------------------------
__device__ int   g_grid[GRIDCELLS];
__device__ float g_buf0[(size_t)MROWS * CDIM];        // conv output (raw fp32)
__device__ float g_buf1[(size_t)MROWS * CDIM];        // bn+relu output / rounded input
__device__ float g_part[RBLOCKS * 2 * CDIM];
__device__ float g_scale[CDIM];
__device__ float g_shift[CDIM];
__device__ float g_projWT[CDIM * CDIM];
__device__ float g_Wst[2 * 27 * BPAD];                // W as [k][cout][cin], stride-68 padded, tf32-rounded

// ---------------------------------------------------------------------------
// Helpers
// ---------------------------------------------------------------------------
__device__ __forceinline__ uint32_t smem_to_u32(const void* p) {
    uint32_t a;
    asm("{ .reg .u64 t; cvta.to.shared.u64 t, %1; cvt.u32.u64 %0, t; }" : "=r"(a) : "l"(p));
    return a;
}
__device__ __forceinline__ float tf32_round(float x) {
    uint32_t u;
    asm("cvt.rna.tf32.f32 %0, %1;" : "=r"(u) : "f"(x));
    return __uint_as_float(u);
}

#define CP_ASYNC16(dst, src) \
    asm volatile("cp.async.cg.shared.global [%0], [%1], 16;" :: "r"(dst), "l"(src) : "memory")
#define CP_COMMIT() asm volatile("cp.async.commit_group;" ::: "memory")
#define STS16_ZERO(dst) \
    asm volatile("st.shared.v4.b32 [%0], {%1, %1, %1, %1};" :: "r"(dst), "r"(0u) : "memory")

// m16n8k8 tf32 MMA, fp32 accumulate, C==D in registers
__device__ __forceinline__ void mma_tf32(float* c,
                                         uint32_t a0, uint32_t a1, uint32_t a2, uint32_t a3,
                                         uint32_t b0, uint32_t b1)
{
    asm volatile("mma.sync.aligned.m16n8k8.row.col.f32.tf32.tf32.f32 "
                 "{%0,%1,%2,%3}, {%4,%5,%6,%7}, {%8,%9}, {%0,%1,%2,%3};"
                 : "+f"(c[0]), "+f"(c[1]), "+f"(c[2]), "+f"(c[3])
                 : "r"(a0), "r"(a1), "r"(a2), "r"(a3), "r"(b0), "r"(b1));
}

// ---------------------------------------------------------------------------
// Grid hash build
// ---------------------------------------------------------------------------
__global__ void init_grid_kernel()
{
    int i = blockIdx.x * 256 + threadIdx.x;
    if (i < GRIDCELLS) g_grid[i] = -1;
}

__global__ void scatter_kernel(const int* __restrict__ coords)
{
    int m = blockIdx.x * 256 + threadIdx.x;
    if (m < MROWS) {
        int x = coords[3 * m + 0];
        int y = coords[3 * m + 1];
        int z = coords[3 * m + 2];
        int b = m / VVOX;
        g_grid[((b * GX + x) * GY + y) * GZ + z] = m;
    }
}

__global__ void transposeW_kernel(const float* __restrict__ W)
{
    int i = blockIdx.x * 256 + threadIdx.x;
    if (i < CDIM * CDIM) {
        int c = i >> 6, j = i & 63;
        g_projWT[j * CDIM + c] = W[i];
    }
}

// W prep: (27, Cin, Cout) -> [k][cout*68 + cin], tf32-rounded
// (padded layout: the conv's B copy is a straight contiguous stream)
__global__ void prepW_kernel(const float* __restrict__ W, float* __restrict__ dst)
{
    int i = blockIdx.x * 256 + threadIdx.x;       // 27 * 4096
    if (i < 27 * 4096) {
        int k = i >> 12;
        int r = i & 4095;
        int cin = r >> 6, cout = r & 63;          // W[k][cin][cout]
        dst[k * BPAD + cout * ASTR + cin] = tf32_round(W[i]);
    }
}

// Round fp32 -> tf32 (rna): pre-round so HW mantissa truncation is exact
__global__ void round_kernel(const float* __restrict__ x, float* __restrict__ y, int n4)
{
    int i = blockIdx.x * 256 + threadIdx.x;
    if (i >= n4) return;
    float4 v = ((const float4*)x)[i];
    v.x = tf32_round(v.x); v.y = tf32_round(v.y);
    v.z = tf32_round(v.z); v.w = tf32_round(v.w);
    ((float4*)y)[i] = v;
}

// ---------------------------------------------------------------------------
// Tensor-core submanifold conv via mma.sync tf32, double-buffered cp.async
// pipeline. CTA = 256 voxel rows x 64 output channels, 8 warps, 1 CTA/SM.
// Warp w: m-block (w&3)*64, n-block (w>>2)*32; 4x4 mma tiles x 8 k-steps.
// Each thread owns voxel row (m0 + tid): coords in registers, gathers its own
// 256B feature row per offset.
// SMEM (floats): A[2][256*68] | B[2][64*68]  = 174080 bytes
// ---------------------------------------------------------------------------
#define OFF_A0  0
#define OFF_A1  (MTILE * ASTR)                    // 17408
#define OFF_B0  (2 * MTILE * ASTR)                // 34816
#define OFF_B1  (OFF_B0 + BPAD)                   // 39168
#define CONV_SMEM ((OFF_B1 + BPAD) * 4)           // 174080 B

__device__ __forceinline__ void conv_issue_tile(
    int k, float* sA, float* sB,
    const float* __restrict__ fin, const float* __restrict__ WstK,
    int px, int py, int pz, int bb, int tid)
{
    // neighbor lookup for this thread's row
    int nidx = -1;
    if (px >= 0) {
        int x = px + (k / 9)       - 1;
        int y = py + ((k / 3) % 3) - 1;
        int z = pz + (k % 3)       - 1;
        if (((unsigned)x < (unsigned)GX) &
            ((unsigned)y < (unsigned)GY) &
            ((unsigned)z < (unsigned)GZ))
            nidx = g_grid[((bb * GX + x) * GY + y) * GZ + z];
    }
    // A: this thread's full 256B row
    uint32_t adst = smem_to_u32(sA + tid * ASTR);
    if (nidx >= 0) {
        const float* src = fin + (size_t)nidx * CDIM;
#pragma unroll
        for (int i = 0; i < 16; i++)
            CP_ASYNC16(adst + i * 16, src + i * 4);
    } else {
#pragma unroll
        for (int i = 0; i < 16; i++)
            STS16_ZERO(adst + i * 16);
    }
    // B: contiguous padded copy, 1088 x 16B
    uint32_t bdst = smem_to_u32(sB);
#pragma unroll
    for (int i = tid; i < BPAD / 4; i += 256)
        CP_ASYNC16(bdst + i * 16, WstK + i * 4);
}

__device__ __forceinline__ void conv_compute_tile(
    const float* __restrict__ sA, const float* __restrict__ sB,
    float acc[4][4][4], int mb, int nb, int g, int t)
{
#pragma unroll
    for (int s = 0; s < 8; s++) {
        const int kk = 8 * s + t;
        uint32_t b0[4], b1[4];
#pragma unroll
        for (int nt = 0; nt < 4; nt++) {
            const float* bp = sB + (nb + nt * 8 + g) * ASTR;
            b0[nt] = __float_as_uint(bp[kk]);
            b1[nt] = __float_as_uint(bp[kk + 4]);
        }
#pragma unroll
        for (int mt = 0; mt < 4; mt++) {
            const float* ap = sA + (mb + mt * 16 + g) * ASTR;
            uint32_t a0 = __float_as_uint(ap[kk]);
            uint32_t a1 = __float_as_uint(ap[8 * ASTR + kk]);
            uint32_t a2 = __float_as_uint(ap[kk + 4]);
            uint32_t a3 = __float_as_uint(ap[8 * ASTR + kk + 4]);
#pragma unroll
            for (int nt = 0; nt < 4; nt++)
                mma_tf32(acc[mt][nt], a0, a1, a2, a3, b0[nt], b1[nt]);
        }
    }
}

__global__ void __launch_bounds__(256, 1)
conv_mma_kernel(const float* __restrict__ fin,
                const int*   __restrict__ coords,
                const float* __restrict__ Wst,
                float*       __restrict__ fout)
{
    extern __shared__ __align__(16) float smem[];

    const int tid = threadIdx.x;
    const int wid = tid >> 5;
    const int lid = tid & 31;
    const int m0  = blockIdx.x * MTILE;

    const int g = lid >> 2;
    const int t = lid & 3;
    const int mb = (wid & 3) * 64;
    const int nb = (wid >> 2) * 32;

    // this thread's voxel row coords (register-resident)
    int px = -1, py = 0, pz = 0, bb = 0;
    {
        int r = m0 + tid;
        if (r < MROWS) {
            px = coords[3 * r + 0];
            py = coords[3 * r + 1];
            pz = coords[3 * r + 2];
            bb = r / VVOX;
        }
    }

    float acc[4][4][4];
#pragma unroll
    for (int mt = 0; mt < 4; mt++)
#pragma unroll
        for (int nt = 0; nt < 4; nt++)
#pragma unroll
            for (int i = 0; i < 4; i++) acc[mt][nt][i] = 0.0f;

    float* A[2] = { smem + OFF_A0, smem + OFF_A1 };
    float* Bm[2] = { smem + OFF_B0, smem + OFF_B1 };

    // prologue: issue tile 0
    conv_issue_tile(0, A[0], Bm[0], fin, Wst, px, py, pz, bb, tid);
    CP_COMMIT();

    for (int k = 0; k < 27; ++k) {
        const int cb = k & 1;
        if (k < 26) {
            conv_issue_tile(k + 1, A[cb ^ 1], Bm[cb ^ 1], fin,
                            Wst + (size_t)(k + 1) * BPAD, px, py, pz, bb, tid);
            CP_COMMIT();
            asm volatile("cp.async.wait_group 1;" ::: "memory");
        } else {
            asm volatile("cp.async.wait_group 0;" ::: "memory");
        }
        __syncthreads();                 // tile k visible to all warps
        conv_compute_tile(A[cb], Bm[cb], acc, mb, nb, g, t);
        __syncthreads();                 // buffer free before next issue cycle
    }

    // epilogue: c0,c1 -> (row g, cols 2t,2t+1); c2,c3 -> row g+8
#pragma unroll
    for (int mt = 0; mt < 4; mt++) {
        int r0 = m0 + mb + mt * 16 + g;
        int r1 = r0 + 8;
#pragma unroll
        for (int nt = 0; nt < 4; nt++) {
            int col = nb + nt * 8 + 2 * t;
            if (r0 < MROWS)
                *(float2*)(fout + (size_t)r0 * CDIM + col) =
                    make_float2(acc[mt][nt][0], acc[mt][nt][1]);
            if (r1 < MROWS)
                *(float2*)(fout + (size_t)r1 * CDIM + col) =
                    make_float2(acc[mt][nt][2], acc[mt][nt][3]);
        }
    }
}

// ---------------------------------------------------------------------------
// BatchNorm (training-mode batch stats) — deterministic two-stage reduction
// ---------------------------------------------------------------------------
__global__ void reduce_partial_kernel(const float* __restrict__ x)
{
    __shared__ float sh[8][CDIM];
    int tid = threadIdx.x;
    int c = tid & 63, g = tid >> 6;
    float s = 0.0f, s2 = 0.0f;
    for (int r = blockIdx.x * 4 + g; r < MROWS; r += RBLOCKS * 4) {
        float v = x[(size_t)r * CDIM + c];
        s  += v;
        s2 += v * v;
    }
    sh[g][c]     = s;
    sh[4 + g][c] = s2;
    __syncthreads();
    if (tid < 64) {
        float a = sh[0][tid] + sh[1][tid] + sh[2][tid] + sh[3][tid];
        float b = sh[4][tid] + sh[5][tid] + sh[6][tid] + sh[7][tid];
        g_part[blockIdx.x * 128 + tid]      = a;
        g_part[blockIdx.x * 128 + 64 + tid] = b;
    }
}

__global__ void reduce_final_kernel(const float* __restrict__ gamma,
                                    const float* __restrict__ beta)
{
    int c = threadIdx.x;
    float s = 0.0f, s2 = 0.0f;
    for (int bb = 0; bb < RBLOCKS; ++bb) {
        s  += g_part[bb * 128 + c];
        s2 += g_part[bb * 128 + 64 + c];
    }
    const float invM = 1.0f / (float)MROWS;
    float mu  = s * invM;
    float var = s2 * invM - mu * mu;
    float r   = rsqrtf(var + 1e-5f);
    float a   = r * gamma[c];
    g_scale[c] = a;
    g_shift[c] = beta[c] - mu * a;
}

// BN+ReLU apply (+optional tf32 pre-round for the next conv layer's input)
__global__ void bn_apply_kernel(const float* __restrict__ x, float* __restrict__ y,
                                int n4, int doRound)
{
    int i = blockIdx.x * blockDim.x + threadIdx.x;
    if (i >= n4) return;
    int c4 = i & 15;
    float4 v = ((const float4*)x)[i];
    float4 a = ((const float4*)g_scale)[c4];
    float4 b = ((const float4*)g_shift)[c4];
    v.x = fmaxf(fmaf(v.x, a.x, b.x), 0.0f);
    v.y = fmaxf(fmaf(v.y, a.y, b.y), 0.0f);
    v.z = fmaxf(fmaf(v.z, a.z, b.z), 0.0f);
    v.w = fmaxf(fmaf(v.w, a.w, b.w), 0.0f);
    if (doRound) {
        v.x = tf32_round(v.x); v.y = tf32_round(v.y);
        v.z = tf32_round(v.z); v.w = tf32_round(v.w);
    }
    ((float4*)y)[i] = v;
}

// ---------------------------------------------------------------------------
// Keypoint gather (+BN2/ReLU applied inline) + mean + residual + projection.
// One 64-thread block per query (b,n).
// ---------------------------------------------------------------------------
__global__ void fuse_kernel(const float* __restrict__ kp,
                            const float* __restrict__ qf,
                            const float* __restrict__ rawFeats,
                            const float* __restrict__ pb,
                            float* __restrict__ outF,
                            float* __restrict__ outI,
                            int writeIdx)
{
    __shared__ float sAvg[CDIM];
    __shared__ int   sIdx[KP];
    int q   = blockIdx.x;
    int tid = threadIdx.x;
    int b   = q >> 13;

    if (tid < KP) {
        const float* kpp = kp + ((size_t)q * KP + tid) * 3;
        int qx = (int)(kpp[0] * 2.0f); qx = min(max(qx, 0), GX - 1);
        int qy = (int)(kpp[1] * 2.0f); qy = min(max(qy, 0), GY - 1);
        int qz = (int)(kpp[2] * 2.0f); qz = min(max(qz, 0), GZ - 1);
        int idx = g_grid[((b * GX + qx) * GY + qy) * GZ + qz];
        sIdx[tid] = (idx < 0) ? 0 : idx;
        if (writeIdx) {
            float* o = outI + ((size_t)q * KP + tid) * 4;
            o[0] = (float)b;
            o[1] = (float)qx;
            o[2] = (float)qy;
            o[3] = (float)qz;
        }
    }
    __syncthreads();

    const float sc = g_scale[tid];
    const float sh = g_shift[tid];
    float s = 0.0f;
#pragma unroll
    for (int kk = 0; kk < KP; kk++) {
        float raw = rawFeats[(size_t)sIdx[kk] * CDIM + tid];
        s += fmaxf(fmaf(raw, sc, sh), 0.0f);    // BN2 + ReLU inline
    }
    s = s * 0.125f + qf[(size_t)q * CDIM + tid];
    sAvg[tid] = s;
    __syncthreads();

    float o = pb[tid];
#pragma unroll 8
    for (int j = 0; j < CDIM; j++)
        o = fmaf(sAvg[j], g_projWT[j * CDIM + tid], o);
    outF[(size_t)q * CDIM + tid] = o;
}

// ---------------------------------------------------------------------------
// Host launcher
// ---------------------------------------------------------------------------
extern "C" void kernel_launch(void* const* d_in, const int* in_sizes, int n_in,
                              void* d_out, int out_size)
{
    const float* keypoints = (const float*)d_in[0];
    const float* query     = (const float*)d_in[1];
    const float* vfeat     = (const float*)d_in[2];
    const int*   vcoords   = (const int*)  d_in[3];
    const float* W1        = (const float*)d_in[4];
    const float* g1        = (const float*)d_in[5];
    const float* b1        = (const float*)d_in[6];
    const float* W2        = (const float*)d_in[7];
    const float* g2        = (const float*)d_in[8];
    const float* b2        = (const float*)d_in[9];
    const float* projW     = (const float*)d_in[10];
    const float* projb     = (const float*)d_in[11];
    float* out = (float*)d_out;

    (void)in_sizes; (void)n_in;

    cudaFuncSetAttribute(conv_mma_kernel, cudaFuncAttributeMaxDynamicSharedMemorySize, CONV_SMEM);

    float *buf0, *buf1, *wst;
    cudaGetSymbolAddress((void**)&buf0, g_buf0);
    cudaGetSymbolAddress((void**)&buf1, g_buf1);
    cudaGetSymbolAddress((void**)&wst,  g_Wst);

    const int fusedElems = BATCH * NQ * CDIM;
    const int idxElems   = BATCH * NQ * KP * 4;
    int writeIdx = (out_size >= fusedElems + idxElems) ? 1 : 0;

    const int convBlocks = (MROWS + MTILE - 1) / MTILE;  // 782
    const int n4         = MROWS * CDIM / 4;             // 3,200,000
    const int bnBlocks   = (n4 + 255) / 256;

    // prep
    init_grid_kernel<<<GRIDCELLS / 256, 256>>>();
    scatter_kernel<<<(MROWS + 255) / 256, 256>>>(vcoords);
    transposeW_kernel<<<16, 256>>>(projW);
    prepW_kernel<<<432, 256>>>(W1, wst);
    prepW_kernel<<<432, 256>>>(W2, wst + 27 * BPAD);
    round_kernel<<<bnBlocks, 256>>>(vfeat, buf1, n4);    // tf32-rounded conv1 input

    // layer 1
    conv_mma_kernel<<<convBlocks, 256, CONV_SMEM>>>(buf1, vcoords, wst, buf0);
    reduce_partial_kernel<<<RBLOCKS, 256>>>(buf0);
    reduce_final_kernel<<<1, 64>>>(g1, b1);
    bn_apply_kernel<<<bnBlocks, 256>>>(buf0, buf1, n4, 1);   // rounded: feeds conv2

    // layer 2 (BN2 folded into fuse)
    conv_mma_kernel<<<convBlocks, 256, CONV_SMEM>>>(buf1, vcoords, wst + 27 * BPAD, buf0);
    reduce_partial_kernel<<<RBLOCKS, 256>>>(buf0);
    reduce_final_kernel<<<1, 64>>>(g2, b2);

    // fuse + project (+ voxel_indices), BN2+ReLU applied on the gathered rows
    fuse_kernel<<<BATCH * NQ, 64>>>(keypoints, query, buf0, projb,
                                    out, out + fusedElems, writeIdx);
}

// round 13
// speedup vs baseline: 2.5250x; 2.5250x over previous
#include <cuda_runtime.h>
#include <cuda_fp16.h>
#include <cstdint>

// ---------------------------------------------------------------------------
// Problem constants
// ---------------------------------------------------------------------------
#define BATCH   2
#define VVOX    100000
#define MROWS   (BATCH * VVOX)     // 200000 voxel rows
#define GX      128
#define GY      128
#define GZ      16
#define CDIM    64
#define NQ      8192
#define KP      8
#define GRIDCELLS (BATCH * GX * GY * GZ)   // 524288
#define RBLOCKS 256

// fp16 operand layout
#define HSTR    72                 // padded smem/global row stride (halves)
#define BPADH   (64 * HSTR)        // 4608 halves per W_k

// ---------------------------------------------------------------------------
// Device scratch (static allocation only)
// ---------------------------------------------------------------------------
__device__ int    g_grid[GRIDCELLS];
__device__ float  g_buf0[(size_t)MROWS * CDIM];       // conv output (fp32)
__device__ __half g_bufh[(size_t)MROWS * CDIM];       // fp16 conv input (rounded / bn+relu)
__device__ float  g_part[RBLOCKS * 2 * CDIM];
__device__ float  g_scale[CDIM];
__device__ float  g_shift[CDIM];
__device__ float  g_projWT[CDIM * CDIM];
__device__ __half g_Wsth[2 * 27 * BPADH];             // W as [k][cout][cin] halves, stride-72

// ---------------------------------------------------------------------------
// Helpers
// ---------------------------------------------------------------------------
__device__ __forceinline__ uint32_t smem_to_u32(const void* p) {
    uint32_t a;
    asm("{ .reg .u64 t; cvta.to.shared.u64 t, %1; cvt.u32.u64 %0, t; }" : "=r"(a) : "l"(p));
    return a;
}

#define CP_ASYNC16(dst, src) \
    asm volatile("cp.async.cg.shared.global [%0], [%1], 16;" :: "r"(dst), "l"(src) : "memory")
#define CP_COMMIT() asm volatile("cp.async.commit_group;" ::: "memory")
#define CP_WAIT0()  asm volatile("cp.async.wait_group 0;" ::: "memory")
#define STS16_ZERO(dst) \
    asm volatile("st.shared.v4.b32 [%0], {%1, %1, %1, %1};" :: "r"(dst), "r"(0u) : "memory")

// m16n8k16 fp16 MMA, fp32 accumulate, C==D in registers
__device__ __forceinline__ void mma_f16(float* c,
                                        uint32_t a0, uint32_t a1, uint32_t a2, uint32_t a3,
                                        uint32_t b0, uint32_t b1)
{
    asm volatile("mma.sync.aligned.m16n8k16.row.col.f32.f16.f16.f32 "
                 "{%0,%1,%2,%3}, {%4,%5,%6,%7}, {%8,%9}, {%0,%1,%2,%3};"
                 : "+f"(c[0]), "+f"(c[1]), "+f"(c[2]), "+f"(c[3])
                 : "r"(a0), "r"(a1), "r"(a2), "r"(a3), "r"(b0), "r"(b1));
}

// ---------------------------------------------------------------------------
// Grid hash build
// ---------------------------------------------------------------------------
__global__ void init_grid_kernel()
{
    int i = blockIdx.x * 256 + threadIdx.x;
    if (i < GRIDCELLS) g_grid[i] = -1;
}

__global__ void scatter_kernel(const int* __restrict__ coords)
{
    int m = blockIdx.x * 256 + threadIdx.x;
    if (m < MROWS) {
        int x = coords[3 * m + 0];
        int y = coords[3 * m + 1];
        int z = coords[3 * m + 2];
        int b = m / VVOX;
        g_grid[((b * GX + x) * GY + y) * GZ + z] = m;
    }
}

__global__ void transposeW_kernel(const float* __restrict__ W)
{
    int i = blockIdx.x * 256 + threadIdx.x;
    if (i < CDIM * CDIM) {
        int c = i >> 6, j = i & 63;
        g_projWT[j * CDIM + c] = W[i];
    }
}

// W prep: (27, Cin, Cout) fp32 -> [k][cout*72 + cin] fp16 (rn)
__global__ void prepW_kernel(const float* __restrict__ W, __half* __restrict__ dst)
{
    int i = blockIdx.x * 256 + threadIdx.x;       // 27 * 4096
    if (i < 27 * 4096) {
        int k = i >> 12;
        int r = i & 4095;
        int cin = r >> 6, cout = r & 63;          // W[k][cin][cout]
        dst[k * BPADH + cout * HSTR + cin] = __float2half_rn(W[i]);
    }
}

// fp32 -> fp16 (rn) conversion of the conv1 input
__global__ void round_kernel(const float* __restrict__ x, __half* __restrict__ y, int n4)
{
    int i = blockIdx.x * 256 + threadIdx.x;
    if (i >= n4) return;
    float4 v = ((const float4*)x)[i];
    __half2* d = (__half2*)y;
    d[2 * i + 0] = __floats2half2_rn(v.x, v.y);
    d[2 * i + 1] = __floats2half2_rn(v.z, v.w);
}

// ---------------------------------------------------------------------------
// Tensor-core submanifold conv via mma.sync fp16 (fp32 accumulate).
// CTA = 128 voxel rows x 64 output channels, 8 warps, ~3 CTAs/SM.
// Warp w: m-block (w&3)*32 (2 mt of 16), n-block (w>>2)*32 (4 nt of 8).
// Per offset: 4 k-chunks of 16 -> 32 HMMA / warp.
// Static SMEM: sA[128][72]h | sB[64][72]h | sN[128] | sP[128]  (~29.7 KB)
// ---------------------------------------------------------------------------
__global__ void __launch_bounds__(256)
conv_mma_kernel(const __half* __restrict__ fin,
                const int*    __restrict__ coords,
                const __half* __restrict__ Wst,
                float*        __restrict__ fout)
{
    __shared__ __align__(16) __half sA[128 * HSTR];
    __shared__ __align__(16) __half sB[64 * HSTR];
    __shared__ int sN[128];
    __shared__ int sP[128];

    const int tid = threadIdx.x;
    const int wid = tid >> 5;
    const int lid = tid & 31;
    const int m0  = blockIdx.x * 128;

    const int g = lid >> 2;          // 0..7
    const int t = lid & 3;           // 0..3
    const int mb = (wid & 3) * 32;
    const int nb = (wid >> 2) * 32;

    if (tid < 128) {
        int r = m0 + tid;
        sP[tid] = (r < MROWS)
                ? ((coords[3 * r] << 11) | (coords[3 * r + 1] << 4) | coords[3 * r + 2])
                : -1;
    }

    float acc[2][4][4];
#pragma unroll
    for (int mt = 0; mt < 2; mt++)
#pragma unroll
        for (int nt = 0; nt < 4; nt++)
#pragma unroll
            for (int i = 0; i < 4; i++) acc[mt][nt][i] = 0.0f;

    // A gather: 2 threads per row, 64B (4 x 16B) each
    const int arow  = tid >> 1;
    const int ahalf = tid & 1;                      // halves 32*ahalf..+31
    const uint32_t adst0 = smem_to_u32(sA) + (uint32_t)(arow * HSTR + ahalf * 32) * 2u;
    const uint32_t bbase = smem_to_u32(sB);

    for (int k = 0; k < 27; ++k) {
        __syncthreads();   // smem free (prev compute done); sP ready on k==0

        if (tid < 128) {
            int nidx = -1;
            int p = sP[tid];
            if (p >= 0) {
                int x = (p >> 11)        + (k / 9)       - 1;
                int y = ((p >> 4) & 127) + ((k / 3) % 3) - 1;
                int z = (p & 15)         + (k % 3)       - 1;
                if (((unsigned)x < (unsigned)GX) &
                    ((unsigned)y < (unsigned)GY) &
                    ((unsigned)z < (unsigned)GZ)) {
                    int b = (m0 + tid) / VVOX;
                    nidx = g_grid[((b * GX + x) * GY + y) * GZ + z];
                }
            }
            sN[tid] = nidx;
        }
        __syncthreads();

        // A gather (fp16 rows: 128B each)
        {
            int nidx = sN[arow];
            if (nidx >= 0) {
                const __half* src = fin + (size_t)nidx * CDIM + ahalf * 32;
#pragma unroll
                for (int i = 0; i < 4; i++)
                    CP_ASYNC16(adst0 + i * 16, src + i * 8);
            } else {
#pragma unroll
                for (int i = 0; i < 4; i++)
                    STS16_ZERO(adst0 + i * 16);
            }
        }
        // B copy: 64*72 halves = 9216B = 576 x 16B
        {
            const __half* srcb = Wst + (size_t)k * BPADH;
#pragma unroll
            for (int i = tid; i < 576; i += 256)
                CP_ASYNC16(bbase + i * 16, srcb + i * 8);
        }
        CP_COMMIT();
        CP_WAIT0();
        __syncthreads();

        // compute: 4 k-chunks x (2 mt x 4 nt) m16n8k16
#pragma unroll
        for (int s = 0; s < 4; s++) {
            const int kc = 16 * s + 2 * t;
            uint32_t b0[4], b1[4];
#pragma unroll
            for (int nt = 0; nt < 4; nt++) {
                const __half* bp = sB + (nb + nt * 8 + g) * HSTR + kc;
                b0[nt] = *(const uint32_t*)(bp);
                b1[nt] = *(const uint32_t*)(bp + 8);
            }
#pragma unroll
            for (int mt = 0; mt < 2; mt++) {
                const __half* ap = sA + (mb + mt * 16 + g) * HSTR + kc;
                uint32_t a0 = *(const uint32_t*)(ap);
                uint32_t a1 = *(const uint32_t*)(ap + 8 * HSTR);
                uint32_t a2 = *(const uint32_t*)(ap + 8);
                uint32_t a3 = *(const uint32_t*)(ap + 8 * HSTR + 8);
#pragma unroll
                for (int nt = 0; nt < 4; nt++)
                    mma_f16(acc[mt][nt], a0, a1, a2, a3, b0[nt], b1[nt]);
            }
        }
    }

    // epilogue: c0,c1 -> (row g, cols 2t,2t+1); c2,c3 -> row g+8
#pragma unroll
    for (int mt = 0; mt < 2; mt++) {
        int r0 = m0 + mb + mt * 16 + g;
        int r1 = r0 + 8;
#pragma unroll
        for (int nt = 0; nt < 4; nt++) {
            int col = nb + nt * 8 + 2 * t;
            if (r0 < MROWS)
                *(float2*)(fout + (size_t)r0 * CDIM + col) =
                    make_float2(acc[mt][nt][0], acc[mt][nt][1]);
            if (r1 < MROWS)
                *(float2*)(fout + (size_t)r1 * CDIM + col) =
                    make_float2(acc[mt][nt][2], acc[mt][nt][3]);
        }
    }
}

// ---------------------------------------------------------------------------
// BatchNorm (training-mode batch stats) — deterministic two-stage reduction
// ---------------------------------------------------------------------------
__global__ void reduce_partial_kernel(const float* __restrict__ x)
{
    __shared__ float sh[8][CDIM];
    int tid = threadIdx.x;
    int c = tid & 63, g = tid >> 6;
    float s = 0.0f, s2 = 0.0f;
    for (int r = blockIdx.x * 4 + g; r < MROWS; r += RBLOCKS * 4) {
        float v = x[(size_t)r * CDIM + c];
        s  += v;
        s2 += v * v;
    }
    sh[g][c]     = s;
    sh[4 + g][c] = s2;
    __syncthreads();
    if (tid < 64) {
        float a = sh[0][tid] + sh[1][tid] + sh[2][tid] + sh[3][tid];
        float b = sh[4][tid] + sh[5][tid] + sh[6][tid] + sh[7][tid];
        g_part[blockIdx.x * 128 + tid]      = a;
        g_part[blockIdx.x * 128 + 64 + tid] = b;
    }
}

__global__ void reduce_final_kernel(const float* __restrict__ gamma,
                                    const float* __restrict__ beta)
{
    int c = threadIdx.x;
    float s = 0.0f, s2 = 0.0f;
    for (int bb = 0; bb < RBLOCKS; ++bb) {
        s  += g_part[bb * 128 + c];
        s2 += g_part[bb * 128 + 64 + c];
    }
    const float invM = 1.0f / (float)MROWS;
    float mu  = s * invM;
    float var = s2 * invM - mu * mu;
    float r   = rsqrtf(var + 1e-5f);
    float a   = r * gamma[c];
    g_scale[c] = a;
    g_shift[c] = beta[c] - mu * a;
}

// BN+ReLU apply, output fp16 (feeds conv2)
__global__ void bn_apply_h_kernel(const float* __restrict__ x, __half* __restrict__ y, int n4)
{
    int i = blockIdx.x * blockDim.x + threadIdx.x;
    if (i >= n4) return;
    int c4 = i & 15;
    float4 v = ((const float4*)x)[i];
    float4 a = ((const float4*)g_scale)[c4];
    float4 b = ((const float4*)g_shift)[c4];
    v.x = fmaxf(fmaf(v.x, a.x, b.x), 0.0f);
    v.y = fmaxf(fmaf(v.y, a.y, b.y), 0.0f);
    v.z = fmaxf(fmaf(v.z, a.z, b.z), 0.0f);
    v.w = fmaxf(fmaf(v.w, a.w, b.w), 0.0f);
    __half2* d = (__half2*)y;
    d[2 * i + 0] = __floats2half2_rn(v.x, v.y);
    d[2 * i + 1] = __floats2half2_rn(v.z, v.w);
}

// ---------------------------------------------------------------------------
// Keypoint gather (+BN2/ReLU inline) + mean + residual + projection.
// ---------------------------------------------------------------------------
__global__ void fuse_kernel(const float* __restrict__ kp,
                            const float* __restrict__ qf,
                            const float* __restrict__ rawFeats,
                            const float* __restrict__ pb,
                            float* __restrict__ outF,
                            float* __restrict__ outI,
                            int writeIdx)
{
    __shared__ float sAvg[CDIM];
    __shared__ int   sIdx[KP];
    int q   = blockIdx.x;
    int tid = threadIdx.x;
    int b   = q >> 13;

    if (tid < KP) {
        const float* kpp = kp + ((size_t)q * KP + tid) * 3;
        int qx = (int)(kpp[0] * 2.0f); qx = min(max(qx, 0), GX - 1);
        int qy = (int)(kpp[1] * 2.0f); qy = min(max(qy, 0), GY - 1);
        int qz = (int)(kpp[2] * 2.0f); qz = min(max(qz, 0), GZ - 1);
        int idx = g_grid[((b * GX + qx) * GY + qy) * GZ + qz];
        sIdx[tid] = (idx < 0) ? 0 : idx;
        if (writeIdx) {
            float* o = outI + ((size_t)q * KP + tid) * 4;
            o[0] = (float)b;
            o[1] = (float)qx;
            o[2] = (float)qy;
            o[3] = (float)qz;
        }
    }
    __syncthreads();

    const float sc = g_scale[tid];
    const float sh = g_shift[tid];
    float s = 0.0f;
#pragma unroll
    for (int kk = 0; kk < KP; kk++) {
        float raw = rawFeats[(size_t)sIdx[kk] * CDIM + tid];
        s += fmaxf(fmaf(raw, sc, sh), 0.0f);    // BN2 + ReLU inline
    }
    s = s * 0.125f + qf[(size_t)q * CDIM + tid];
    sAvg[tid] = s;
    __syncthreads();

    float o = pb[tid];
#pragma unroll 8
    for (int j = 0; j < CDIM; j++)
        o = fmaf(sAvg[j], g_projWT[j * CDIM + tid], o);
    outF[(size_t)q * CDIM + tid] = o;
}

// ---------------------------------------------------------------------------
// Host launcher
// ---------------------------------------------------------------------------
extern "C" void kernel_launch(void* const* d_in, const int* in_sizes, int n_in,
                              void* d_out, int out_size)
{
    const float* keypoints = (const float*)d_in[0];
    const float* query     = (const float*)d_in[1];
    const float* vfeat     = (const float*)d_in[2];
    const int*   vcoords   = (const int*)  d_in[3];
    const float* W1        = (const float*)d_in[4];
    const float* g1        = (const float*)d_in[5];
    const float* b1        = (const float*)d_in[6];
    const float* W2        = (const float*)d_in[7];
    const float* g2        = (const float*)d_in[8];
    const float* b2        = (const float*)d_in[9];
    const float* projW     = (const float*)d_in[10];
    const float* projb     = (const float*)d_in[11];
    float* out = (float*)d_out;

    (void)in_sizes; (void)n_in;

    float  *buf0;
    __half *bufh, *wsth;
    cudaGetSymbolAddress((void**)&buf0, g_buf0);
    cudaGetSymbolAddress((void**)&bufh, g_bufh);
    cudaGetSymbolAddress((void**)&wsth, g_Wsth);

    const int fusedElems = BATCH * NQ * CDIM;
    const int idxElems   = BATCH * NQ * KP * 4;
    int writeIdx = (out_size >= fusedElems + idxElems) ? 1 : 0;

    const int convBlocks = (MROWS + 127) / 128;          // 1563
    const int n4         = MROWS * CDIM / 4;             // 3,200,000
    const int bnBlocks   = (n4 + 255) / 256;

    // prep
    init_grid_kernel<<<GRIDCELLS / 256, 256>>>();
    scatter_kernel<<<(MROWS + 255) / 256, 256>>>(vcoords);
    transposeW_kernel<<<16, 256>>>(projW);
    prepW_kernel<<<432, 256>>>(W1, wsth);
    prepW_kernel<<<432, 256>>>(W2, wsth + 27 * BPADH);
    round_kernel<<<bnBlocks, 256>>>(vfeat, bufh, n4);    // fp16 conv1 input

    // layer 1
    conv_mma_kernel<<<convBlocks, 256>>>(bufh, vcoords, wsth, buf0);
    reduce_partial_kernel<<<RBLOCKS, 256>>>(buf0);
    reduce_final_kernel<<<1, 64>>>(g1, b1);
    bn_apply_h_kernel<<<bnBlocks, 256>>>(buf0, bufh, n4);    // fp16: feeds conv2

    // layer 2 (BN2 folded into fuse)
    conv_mma_kernel<<<convBlocks, 256>>>(bufh, vcoords, wsth + 27 * BPADH, buf0);
    reduce_partial_kernel<<<RBLOCKS, 256>>>(buf0);
    reduce_final_kernel<<<1, 64>>>(g2, b2);

    // fuse + project (+ voxel_indices), BN2+ReLU applied on the gathered rows
    fuse_kernel<<<BATCH * NQ, 64>>>(keypoints, query, buf0, projb,
                                    out, out + fusedElems, writeIdx);
}